// round 1
// baseline (speedup 1.0000x reference)
#include <cuda_runtime.h>
#include <cuda_bf16.h>

// ---------------------------------------------------------------------------
// Problem constants (fixed shapes from reference setup_inputs)
//   tokens T = B*S = 4096, D = 1024, W = 4096, SLOT = 8, C = 11, depth 3
// ---------------------------------------------------------------------------
#define NTOK  4096
#define NDIM  1024
#define NW    4096
#define NSLOT 8
#define SELROW 72   // 8 leaves * (8 weights + 1 bias)

// Scratch (device globals: allocation-free)
__device__ float g_basisT[NSLOT * NTOK];        // [8][4096] transposed basis (slots only)
__device__ float g_sel[NW * SELROW];            // per-w folded selector table
__device__ float g_roots[(size_t)NTOK * NW];    // [4096][4096] = 64 MB

// ---------------------------------------------------------------------------
// fast tanh: (e^{2x}-1)/(e^{2x}+1) with MUFU ex2/rcp, ~1e-6 rel error
// ---------------------------------------------------------------------------
__device__ __forceinline__ float ftanh(float x) {
    x = fminf(fmaxf(x, -15.f), 15.f);
    float e = __expf(2.f * x);
    return __fdividef(e - 1.f, e + 1.f);
}

// ---------------------------------------------------------------------------
// Kernel A: slots = tanh(hidden @ slot_w + slot_b), stored transposed [8][T]
// one warp per token
// ---------------------------------------------------------------------------
__global__ __launch_bounds__(256) void kA(const float* __restrict__ hidden,
                                          const float* __restrict__ sw,
                                          const float* __restrict__ sb,
                                          float* __restrict__ basisT) {
    const int wid  = threadIdx.x >> 5;
    const int lane = threadIdx.x & 31;
    const int token = blockIdx.x * 8 + wid;
    const float* h = hidden + (size_t)token * NDIM;

    float acc[8] = {0.f, 0.f, 0.f, 0.f, 0.f, 0.f, 0.f, 0.f};
    for (int d0 = 0; d0 < NDIM; d0 += 128) {
        float4 hv = *(const float4*)(h + d0 + lane * 4);
        const float* hp = (const float*)&hv;
#pragma unroll
        for (int j = 0; j < 4; j++) {
            const float4* wr = (const float4*)(sw + (size_t)(d0 + lane * 4 + j) * NSLOT);
            float4 w0 = wr[0], w1 = wr[1];
            float hj = hp[j];
            acc[0] = fmaf(hj, w0.x, acc[0]);
            acc[1] = fmaf(hj, w0.y, acc[1]);
            acc[2] = fmaf(hj, w0.z, acc[2]);
            acc[3] = fmaf(hj, w0.w, acc[3]);
            acc[4] = fmaf(hj, w1.x, acc[4]);
            acc[5] = fmaf(hj, w1.y, acc[5]);
            acc[6] = fmaf(hj, w1.z, acc[6]);
            acc[7] = fmaf(hj, w1.w, acc[7]);
        }
    }
#pragma unroll
    for (int k = 0; k < 8; k++) {
        float v = acc[k];
#pragma unroll
        for (int off = 16; off; off >>= 1) v += __shfl_xor_sync(0xFFFFFFFFu, v, off);
        if (lane == k) basisT[k * NTOK + token] = ftanh(v + sb[k]);
    }
}

// ---------------------------------------------------------------------------
// Kernel B: fold softmax(leaf_logits) into 8 weights + 1 bias per (w,leaf)
//   bias = sel[10] - sel[8]   (constants -1,0,1 folded)
// one thread per (w, leaf)
// ---------------------------------------------------------------------------
__global__ __launch_bounds__(256) void kB(const float* __restrict__ logits,
                                          float* __restrict__ sel) {
    const int t = blockIdx.x * 256 + threadIdx.x;     // 0..32767
    const float* p = logits + (size_t)t * 11;
    float x[11], mx = -1e30f;
#pragma unroll
    for (int c = 0; c < 11; c++) { x[c] = p[c]; mx = fmaxf(mx, x[c]); }
    float s = 0.f;
#pragma unroll
    for (int c = 0; c < 11; c++) { x[c] = __expf(x[c] - mx); s += x[c]; }
    const float inv = 1.0f / s;
    const int w = t >> 3, l = t & 7;
    float* o = sel + (size_t)w * SELROW + l * 9;
#pragma unroll
    for (int k = 0; k < 8; k++) o[k] = x[k] * inv;
    o[8] = (x[10] - x[8]) * inv;
}

// ---------------------------------------------------------------------------
// Kernel C: roots[t][w] = tree-reduce of 8 leaf values
// tile 128 tokens x 128 w; lane indexes w (coalesced root stores),
// selector rows padded to 73 floats for conflict-free LDS,
// basis reads are warp-broadcast.
// ---------------------------------------------------------------------------
__device__ __forceinline__ float node_fn(float l, float r, float lw, float rw,
                                         float pw, float dw, float nb) {
    float a = fmaf(lw, l, nb);
    a = fmaf(rw, r, a);
    a = fmaf(pw, l * r, a);
    a = fmaf(dw, l - r, a);
    return ftanh(a);
}

__global__ __launch_bounds__(256) void kC(const float* __restrict__ np,
                                          const float* __restrict__ sel,
                                          const float* __restrict__ basisT,
                                          float* __restrict__ roots) {
    __shared__ float ssel[128 * 73];
    __shared__ float sbas[8 * 128];
    const int tid = threadIdx.x;
    const int wblk = blockIdx.x * 128;
    const int tblk = blockIdx.y * 128;

    for (int i = tid; i < 128 * SELROW; i += 256) {
        int w = i / SELROW, r = i - w * SELROW;
        ssel[w * 73 + r] = sel[(size_t)(wblk + w) * SELROW + r];
    }
    for (int i = tid; i < 8 * 128; i += 256) {
        int k = i >> 7, t = i & 127;
        sbas[i] = basisT[k * NTOK + tblk + t];
    }
    __syncthreads();

    const float lw = np[0], rw = np[1], pw = np[2], dw = np[3], nb = np[4];
    const int wid = tid >> 5, lane = tid & 31;
    const int wloc  = (wid & 3) * 32 + lane;  // 0..127 within tile
    const int thalf = (wid >> 2) * 64;        // token half 0 or 64
    const float* mysel = ssel + wloc * 73;
    float* rbase = roots + (size_t)(tblk + thalf) * NW + wblk + wloc;

    for (int tb = 0; tb < 64; tb += 4) {
        float bs[4][8];
#pragma unroll
        for (int t = 0; t < 4; t++)
#pragma unroll
            for (int k = 0; k < 8; k++) bs[t][k] = sbas[k * 128 + thalf + tb + t];

        float v[4][8];
#pragma unroll
        for (int l = 0; l < 8; l++) {
            float s0 = mysel[l * 9 + 0], s1 = mysel[l * 9 + 1];
            float s2 = mysel[l * 9 + 2], s3 = mysel[l * 9 + 3];
            float s4 = mysel[l * 9 + 4], s5 = mysel[l * 9 + 5];
            float s6 = mysel[l * 9 + 6], s7 = mysel[l * 9 + 7];
            float sbv = mysel[l * 9 + 8];
#pragma unroll
            for (int t = 0; t < 4; t++) {
                float a = fmaf(s0, bs[t][0], sbv);
                a = fmaf(s1, bs[t][1], a);
                a = fmaf(s2, bs[t][2], a);
                a = fmaf(s3, bs[t][3], a);
                a = fmaf(s4, bs[t][4], a);
                a = fmaf(s5, bs[t][5], a);
                a = fmaf(s6, bs[t][6], a);
                a = fmaf(s7, bs[t][7], a);
                v[t][l] = a;
            }
        }
#pragma unroll
        for (int t = 0; t < 4; t++) {
            float n0 = node_fn(v[t][0], v[t][1], lw, rw, pw, dw, nb);
            float n1 = node_fn(v[t][2], v[t][3], lw, rw, pw, dw, nb);
            float n2 = node_fn(v[t][4], v[t][5], lw, rw, pw, dw, nb);
            float n3 = node_fn(v[t][6], v[t][7], lw, rw, pw, dw, nb);
            float m0 = node_fn(n0, n1, lw, rw, pw, dw, nb);
            float m1 = node_fn(n2, n3, lw, rw, pw, dw, nb);
            rbase[(size_t)(tb + t) * NW] = node_fn(m0, m1, lw, rw, pw, dw, nb);
        }
    }
}

// ---------------------------------------------------------------------------
// Kernel D: out = roots @ out_w + out_b   (M=4096, K=4096, N=1024)
// tf32 mma.sync m16n8k8, 128x128x16 tiles, double-buffered smem
// ---------------------------------------------------------------------------
__device__ __forceinline__ unsigned int cvt_tf32(float x) {
    unsigned int r;
    asm("cvt.rna.tf32.f32 %0, %1;" : "=r"(r) : "f"(x));
    return r;
}

#define SA_STRIDE 20
#define SB_STRIDE 136

__global__ __launch_bounds__(256, 2) void kD(const float* __restrict__ A,
                                             const float* __restrict__ B,
                                             const float* __restrict__ bias,
                                             float* __restrict__ C) {
    __shared__ float sA[2][128 * SA_STRIDE];
    __shared__ float sB[2][16 * SB_STRIDE];

    const int tid = threadIdx.x, wid = tid >> 5, lane = tid & 31;
    const int bm = blockIdx.y, bn = blockIdx.x;
    const int warp_m = wid >> 2;   // 0..1 (64-row halves)
    const int warp_n = wid & 3;    // 0..3 (32-col quarters)

    // global staging addresses
    const int arow = tid >> 2, aquad = tid & 3;          // A: rows arow, arow+64
    const int brow = tid >> 5, bcol = (tid & 31) * 4;    // B: k-rows brow, brow+8
    const float* gA = A + (size_t)(bm * 128 + arow) * NW + aquad * 4;
    const float* gB = B + (size_t)brow * NDIM + bn * 128 + bcol;

    float acc[4][4][4];
#pragma unroll
    for (int i = 0; i < 4; i++)
#pragma unroll
        for (int j = 0; j < 4; j++)
#pragma unroll
            for (int k = 0; k < 4; k++) acc[i][j][k] = 0.f;

    // preload buffer 0
    {
#pragma unroll
        for (int j = 0; j < 2; j++) {
            float4 v = *(const float4*)(gA + (size_t)j * 64 * NW);
            *(float4*)&sA[0][(arow + j * 64) * SA_STRIDE + aquad * 4] = v;
        }
#pragma unroll
        for (int j = 0; j < 2; j++) {
            float4 v = *(const float4*)(gB + (size_t)(j * 8) * NDIM);
            *(float4*)&sB[0][(brow + j * 8) * SB_STRIDE + bcol] = v;
        }
    }
    __syncthreads();

    const int am0 = warp_m * 64 + (lane >> 2);
    const int ak0 = lane & 3;
    const int bn0 = warp_n * 32 + (lane >> 2);
    const int bk0 = lane & 3;

    for (int k0 = 0; k0 < NW; k0 += 16) {
        const int buf = (k0 >> 4) & 1, nbuf = buf ^ 1;
        const bool more = (k0 + 16) < NW;

        float4 ra[2], rb[2];
        if (more) {
#pragma unroll
            for (int j = 0; j < 2; j++)
                ra[j] = *(const float4*)(gA + k0 + 16 + (size_t)j * 64 * NW);
#pragma unroll
            for (int j = 0; j < 2; j++)
                rb[j] = *(const float4*)(gB + (size_t)(k0 + 16 + j * 8) * NDIM);
        }

#pragma unroll
        for (int ks = 0; ks < 2; ks++) {
            unsigned int afr[4][4];
#pragma unroll
            for (int mi = 0; mi < 4; mi++) {
                int r = am0 + mi * 16;
                afr[mi][0] = cvt_tf32(sA[buf][r * SA_STRIDE + ks * 8 + ak0]);
                afr[mi][1] = cvt_tf32(sA[buf][(r + 8) * SA_STRIDE + ks * 8 + ak0]);
                afr[mi][2] = cvt_tf32(sA[buf][r * SA_STRIDE + ks * 8 + ak0 + 4]);
                afr[mi][3] = cvt_tf32(sA[buf][(r + 8) * SA_STRIDE + ks * 8 + ak0 + 4]);
            }
            unsigned int bfr[4][2];
#pragma unroll
            for (int ni = 0; ni < 4; ni++) {
                int c = bn0 + ni * 8;
                bfr[ni][0] = cvt_tf32(sB[buf][(ks * 8 + bk0) * SB_STRIDE + c]);
                bfr[ni][1] = cvt_tf32(sB[buf][(ks * 8 + bk0 + 4) * SB_STRIDE + c]);
            }
#pragma unroll
            for (int mi = 0; mi < 4; mi++)
#pragma unroll
                for (int ni = 0; ni < 4; ni++) {
                    asm volatile(
                        "mma.sync.aligned.m16n8k8.row.col.f32.tf32.tf32.f32 "
                        "{%0,%1,%2,%3}, {%4,%5,%6,%7}, {%8,%9}, {%0,%1,%2,%3};\n"
                        : "+f"(acc[mi][ni][0]), "+f"(acc[mi][ni][1]),
                          "+f"(acc[mi][ni][2]), "+f"(acc[mi][ni][3])
                        : "r"(afr[mi][0]), "r"(afr[mi][1]), "r"(afr[mi][2]), "r"(afr[mi][3]),
                          "r"(bfr[ni][0]), "r"(bfr[ni][1]));
                }
        }

        if (more) {
#pragma unroll
            for (int j = 0; j < 2; j++)
                *(float4*)&sA[nbuf][(arow + j * 64) * SA_STRIDE + aquad * 4] = ra[j];
#pragma unroll
            for (int j = 0; j < 2; j++)
                *(float4*)&sB[nbuf][(brow + j * 8) * SB_STRIDE + bcol] = rb[j];
        }
        __syncthreads();
    }

    // epilogue: add bias, float2 stores
    const int gm0 = bm * 128 + warp_m * 64 + (lane >> 2);
#pragma unroll
    for (int mi = 0; mi < 4; mi++) {
#pragma unroll
        for (int ni = 0; ni < 4; ni++) {
            int col = bn * 128 + warp_n * 32 + ni * 8 + (lane & 3) * 2;
            float b0 = __ldg(bias + col), b1 = __ldg(bias + col + 1);
            int r0 = gm0 + mi * 16;
            float2 v0 = make_float2(acc[mi][ni][0] + b0, acc[mi][ni][1] + b1);
            float2 v1 = make_float2(acc[mi][ni][2] + b0, acc[mi][ni][3] + b1);
            *(float2*)(C + (size_t)r0 * NDIM + col) = v0;
            *(float2*)(C + (size_t)(r0 + 8) * NDIM + col) = v1;
        }
    }
}

// ---------------------------------------------------------------------------
// launch
// inputs: 0 hidden, 1 slot_w, 2 slot_b, 3 leaf_logits, 4 node_params,
//         5 out_w, 6 out_b ; output float32 [4096,1024]
// ---------------------------------------------------------------------------
extern "C" void kernel_launch(void* const* d_in, const int* in_sizes, int n_in,
                              void* d_out, int out_size) {
    const float* hidden      = (const float*)d_in[0];
    const float* slot_w      = (const float*)d_in[1];
    const float* slot_b      = (const float*)d_in[2];
    const float* leaf_logits = (const float*)d_in[3];
    const float* node_params = (const float*)d_in[4];
    const float* out_w       = (const float*)d_in[5];
    const float* out_b       = (const float*)d_in[6];
    float* out = (float*)d_out;

    float* basisT; cudaGetSymbolAddress((void**)&basisT, g_basisT);
    float* sel;    cudaGetSymbolAddress((void**)&sel,    g_sel);
    float* roots;  cudaGetSymbolAddress((void**)&roots,  g_roots);

    kA<<<NTOK / 8, 256>>>(hidden, slot_w, slot_b, basisT);
    kB<<<(NW * 8) / 256, 256>>>(leaf_logits, sel);
    dim3 gc(NW / 128, NTOK / 128);
    kC<<<gc, 256>>>(node_params, sel, basisT, roots);
    dim3 gd(NDIM / 128, NTOK / 128);
    kD<<<gd, 256>>>(roots, out_w, out_b, out);
}

// round 9
// speedup vs baseline: 1.7242x; 1.7242x over previous
#include <cuda.h>
#include <cuda_runtime.h>
#include <cuda_fp16.h>
#include <cstdint>

// ---------------------------------------------------------------------------
// Shapes: tokens T = 4096, D = 1024, W = 4096, SLOT = 8, depth 3
// ---------------------------------------------------------------------------
#define NTOK  4096
#define NDIM  1024
#define NW    4096
#define NSLOT 8
#define SELROW 72

// Scratch (device globals: allocation-free)
__device__ __align__(1024) float  g_basisT[NSLOT * NTOK];
__device__ __align__(1024) float  g_sel[NW * SELROW];
__device__ __align__(1024) __half g_roots[(size_t)NTOK * NW];   // 32 MB fp16
__device__ __align__(1024) __half g_outwT[(size_t)NDIM * NW];   // 8 MB fp16 [n][k]

typedef unsigned long long u64;

// ---------------------------------------------------------------------------
// helpers
// ---------------------------------------------------------------------------
__device__ __forceinline__ float ftanh(float x) {
    x = fminf(fmaxf(x, -15.f), 15.f);
    float e = __expf(2.f * x);
    return __fdividef(e - 1.f, e + 1.f);
}
__device__ __forceinline__ uint32_t s2u(const void* p) {
    uint32_t a;
    asm("{ .reg .u64 t; cvta.to.shared.u64 t, %1; cvt.u32.u64 %0, t; }" : "=r"(a) : "l"(p));
    return a;
}

// packed f32x2 ops (FFMA2 path, non-'a' sm_103)
__device__ __forceinline__ u64 pk(float lo, float hi) {
    u64 r; asm("mov.b64 %0,{%1,%2};" : "=l"(r) : "f"(lo), "f"(hi)); return r;
}
__device__ __forceinline__ u64 pk1(float x) { return pk(x, x); }
__device__ __forceinline__ void upk(u64 v, float& lo, float& hi) {
    asm("mov.b64 {%0,%1},%2;" : "=f"(lo), "=f"(hi) : "l"(v));
}
__device__ __forceinline__ u64 f2fma(u64 a, u64 b, u64 c) {
    u64 d; asm("fma.rn.f32x2 %0,%1,%2,%3;" : "=l"(d) : "l"(a), "l"(b), "l"(c)); return d;
}
__device__ __forceinline__ u64 f2mul(u64 a, u64 b) {
    u64 d; asm("mul.rn.f32x2 %0,%1,%2;" : "=l"(d) : "l"(a), "l"(b)); return d;
}
// packed tanh; input pre-scaled by 2*log2(e)
__device__ __forceinline__ u64 ptanh2(u64 a2) {
    float a0, a1; upk(a2, a0, a1);
    a0 = fminf(fmaxf(a0, -80.f), 80.f);
    a1 = fminf(fmaxf(a1, -80.f), 80.f);
    float e0, e1, r0, r1;
    asm("ex2.approx.f32 %0,%1;" : "=f"(e0) : "f"(a0));
    asm("ex2.approx.f32 %0,%1;" : "=f"(e1) : "f"(a1));
    float d0 = e0 + 1.f, d1 = e1 + 1.f;
    asm("rcp.approx.f32 %0,%1;" : "=f"(r0) : "f"(d0));
    asm("rcp.approx.f32 %0,%1;" : "=f"(r1) : "f"(d1));
    return pk(fmaf(e0, r0, -r0), fmaf(e1, r1, -r1));
}
__device__ __forceinline__ u64 node2(u64 l, u64 r, u64 LW, u64 RW, u64 PW,
                                     u64 DWP, u64 DWN, u64 NB) {
    u64 a = f2fma(LW, l, NB);
    a = f2fma(RW, r, a);
    a = f2fma(PW, f2mul(l, r), a);
    a = f2fma(DWP, l, a);
    a = f2fma(DWN, r, a);
    return ptanh2(a);
}

// ---------------------------------------------------------------------------
// Kernel A: slots = tanh(hidden @ slot_w + slot_b), stored transposed [8][T]
// ---------------------------------------------------------------------------
__global__ __launch_bounds__(256) void kA(const float* __restrict__ hidden,
                                          const float* __restrict__ sw,
                                          const float* __restrict__ sb,
                                          float* __restrict__ basisT) {
    const int wid = threadIdx.x >> 5, lane = threadIdx.x & 31;
    const int token = blockIdx.x * 8 + wid;
    const float* h = hidden + (size_t)token * NDIM;

    float acc[8] = {0, 0, 0, 0, 0, 0, 0, 0};
    for (int d0 = 0; d0 < NDIM; d0 += 128) {
        float4 hv = *(const float4*)(h + d0 + lane * 4);
        const float* hp = (const float*)&hv;
#pragma unroll
        for (int j = 0; j < 4; j++) {
            const float4* wr = (const float4*)(sw + (size_t)(d0 + lane * 4 + j) * NSLOT);
            float4 w0 = wr[0], w1 = wr[1];
            float hj = hp[j];
            acc[0] = fmaf(hj, w0.x, acc[0]); acc[1] = fmaf(hj, w0.y, acc[1]);
            acc[2] = fmaf(hj, w0.z, acc[2]); acc[3] = fmaf(hj, w0.w, acc[3]);
            acc[4] = fmaf(hj, w1.x, acc[4]); acc[5] = fmaf(hj, w1.y, acc[5]);
            acc[6] = fmaf(hj, w1.z, acc[6]); acc[7] = fmaf(hj, w1.w, acc[7]);
        }
    }
#pragma unroll
    for (int k = 0; k < 8; k++) {
        float v = acc[k];
#pragma unroll
        for (int off = 16; off; off >>= 1) v += __shfl_xor_sync(0xFFFFFFFFu, v, off);
        if (lane == k) basisT[k * NTOK + token] = ftanh(v + sb[k]);
    }
}

// ---------------------------------------------------------------------------
// Kernel B: fold softmax into 8 weights + 1 bias per (w,leaf)
// ---------------------------------------------------------------------------
__global__ __launch_bounds__(256) void kB(const float* __restrict__ logits,
                                          float* __restrict__ sel) {
    const int t = blockIdx.x * 256 + threadIdx.x;
    const float* p = logits + (size_t)t * 11;
    float x[11], mx = -1e30f;
#pragma unroll
    for (int c = 0; c < 11; c++) { x[c] = p[c]; mx = fmaxf(mx, x[c]); }
    float s = 0.f;
#pragma unroll
    for (int c = 0; c < 11; c++) { x[c] = __expf(x[c] - mx); s += x[c]; }
    const float inv = 1.0f / s;
    const int w = t >> 3, l = t & 7;
    float* o = sel + (size_t)w * SELROW + l * 9;
#pragma unroll
    for (int k = 0; k < 8; k++) o[k] = x[k] * inv;
    o[8] = (x[10] - x[8]) * inv;
}

// ---------------------------------------------------------------------------
// Kernel T: out_wT[n][k] = fp16(out_w[k][n])   ([4096,1024] -> [1024,4096])
// ---------------------------------------------------------------------------
__global__ __launch_bounds__(256) void kT(const float* __restrict__ w,
                                          __half* __restrict__ wt) {
    __shared__ float t[32][33];
    const int n0 = blockIdx.x * 32, k0 = blockIdx.y * 32;
#pragma unroll
    for (int j = 0; j < 4; j++)
        t[threadIdx.y + j * 8][threadIdx.x] =
            w[(size_t)(k0 + threadIdx.y + j * 8) * NDIM + n0 + threadIdx.x];
    __syncthreads();
#pragma unroll
    for (int j = 0; j < 4; j++)
        wt[(size_t)(n0 + threadIdx.y + j * 8) * NW + k0 + threadIdx.x] =
            __float2half_rn(t[threadIdx.x][threadIdx.y + j * 8]);
}

// ---------------------------------------------------------------------------
// Kernel C: roots[t][w] via packed f32x2 (2 tokens / instruction), fp16 out
// ---------------------------------------------------------------------------
__global__ __launch_bounds__(256) void kC(const float* __restrict__ np,
                                          const float* __restrict__ sel,
                                          const float* __restrict__ basisT,
                                          __half* __restrict__ roots) {
    __shared__ float ssel[128 * 73];
    __shared__ float sbas[8 * 128];
    const int tid = threadIdx.x;
    const int wblk = blockIdx.x * 128;
    const int tblk = blockIdx.y * 128;

    for (int i = tid; i < 128 * SELROW; i += 256) {
        int w = i / SELROW, r = i - w * SELROW;
        ssel[w * 73 + r] = sel[(size_t)(wblk + w) * SELROW + r];
    }
    for (int i = tid; i < 8 * 128; i += 256) {
        int k = i >> 7, t = i & 127;
        sbas[i] = basisT[k * NTOK + tblk + t];
    }
    __syncthreads();

    const float S = 2.885390081777927f;  // 2*log2(e)
    const u64 LW = pk1(np[0] * S), RW = pk1(np[1] * S), PW = pk1(np[2] * S);
    const u64 DWP = pk1(np[3] * S), DWN = pk1(-np[3] * S), NB = pk1(np[4] * S);

    const int wid = tid >> 5, lane = tid & 31;
    const int wloc = (wid & 3) * 32 + lane;
    const int thalf = (wid >> 2) * 64;
    const float* mysel = ssel + wloc * 73;
    __half* rbase = roots + (size_t)(tblk + thalf) * NW + wblk + wloc;

    for (int tb = 0; tb < 64; tb += 4) {
        u64 bs0[8], bs1[8];
#pragma unroll
        for (int k = 0; k < 8; k++) {
            bs0[k] = *(const u64*)&sbas[k * 128 + thalf + tb];
            bs1[k] = *(const u64*)&sbas[k * 128 + thalf + tb + 2];
        }
        u64 v0[8], v1[8];
#pragma unroll
        for (int l = 0; l < 8; l++) {
            const float* sl = mysel + l * 9;
            u64 a0 = pk1(sl[8]), a1 = a0;
#pragma unroll
            for (int j = 0; j < 8; j++) {
                u64 wj = pk1(sl[j]);
                a0 = f2fma(wj, bs0[j], a0);
                a1 = f2fma(wj, bs1[j], a1);
            }
            v0[l] = a0; v1[l] = a1;
        }
#pragma unroll
        for (int p = 0; p < 2; p++) {
            u64* v = p ? v1 : v0;
            u64 n0 = node2(v[0], v[1], LW, RW, PW, DWP, DWN, NB);
            u64 n1 = node2(v[2], v[3], LW, RW, PW, DWP, DWN, NB);
            u64 n2 = node2(v[4], v[5], LW, RW, PW, DWP, DWN, NB);
            u64 n3 = node2(v[6], v[7], LW, RW, PW, DWP, DWN, NB);
            u64 m0 = node2(n0, n1, LW, RW, PW, DWP, DWN, NB);
            u64 m1 = node2(n2, n3, LW, RW, PW, DWP, DWN, NB);
            u64 rt = node2(m0, m1, LW, RW, PW, DWP, DWN, NB);
            float r0, r1; upk(rt, r0, r1);
            rbase[(size_t)(tb + p * 2) * NW]     = __float2half_rn(r0);
            rbase[(size_t)(tb + p * 2 + 1) * NW] = __float2half_rn(r1);
        }
    }
}

// ---------------------------------------------------------------------------
// Kernel D: out = roots @ out_wT^T + out_b, fp16 HMMA m16n8k16
//   CTA tile 128x128, K-step 32 halfs (64B rows), 3-stage cp.async pipeline,
//   ldmatrix.x4 fragment loads, XOR-swizzled smem (16B chunk ^ (row>>1)&3).
// ---------------------------------------------------------------------------
#define KD_ITERS (NW / 32)   // 128
#define KD_STAGE 16384       // A 8KB + B 8KB

__device__ __forceinline__ void cpa16(uint32_t dst, const void* src) {
    asm volatile("cp.async.cg.shared.global [%0], [%1], 16;" :: "r"(dst), "l"(src) : "memory");
}

__global__ __launch_bounds__(256, 2) void kD(const __half* __restrict__ A,
                                             const __half* __restrict__ B,
                                             const float* __restrict__ bias,
                                             float* __restrict__ C) {
    __shared__ __align__(128) char smem[3 * KD_STAGE];
    const uint32_t sb = s2u(smem);
    const int tid = threadIdx.x, wid = tid >> 5, lane = tid & 31;
    const int bm = blockIdx.y, bn = blockIdx.x;
    const int warp_m = wid >> 2, warp_n = wid & 3;

    // ---- staging: each thread copies 2 A-chunks + 2 B-chunks of 16B per iter
    const int r0 = tid >> 2, c0 = tid & 3, r1 = r0 + 64;
    const uint32_t sA0 = r0 * 64 + ((c0 ^ ((r0 >> 1) & 3)) << 4);
    const uint32_t sA1 = r1 * 64 + ((c0 ^ ((r1 >> 1) & 3)) << 4);
    const __half* gA0 = A + (size_t)(bm * 128 + r0) * NW + c0 * 8;
    const __half* gA1 = A + (size_t)(bm * 128 + r1) * NW + c0 * 8;
    const __half* gB0 = B + (size_t)(bn * 128 + r0) * NW + c0 * 8;
    const __half* gB1 = B + (size_t)(bn * 128 + r1) * NW + c0 * 8;

    // ---- ldmatrix source addresses (per-lane, stage-relative)
    const int mat = lane >> 3, lrow = lane & 7;
    uint32_t adA[4][2], adB[2][2];
#pragma unroll
    for (int mi = 0; mi < 4; mi++) {
        int row = warp_m * 64 + mi * 16 + (mat & 1) * 8 + lrow;
        int coff = mat >> 1, sw = (row >> 1) & 3;
#pragma unroll
        for (int ks = 0; ks < 2; ks++)
            adA[mi][ks] = row * 64 + (((ks * 2 + coff) ^ sw) << 4);
    }
#pragma unroll
    for (int p = 0; p < 2; p++) {
        int nrow = warp_n * 32 + p * 16 + (mat >> 1) * 8 + lrow;
        int coff = mat & 1, sw = (nrow >> 1) & 3;
#pragma unroll
        for (int ks = 0; ks < 2; ks++)
            adB[p][ks] = 8192 + nrow * 64 + (((ks * 2 + coff) ^ sw) << 4);
    }

    float acc[4][4][4];
#pragma unroll
    for (int i = 0; i < 4; i++)
#pragma unroll
        for (int j = 0; j < 4; j++)
#pragma unroll
            for (int k = 0; k < 4; k++) acc[i][j][k] = 0.f;

    // prologue: stages 0,1
#pragma unroll
    for (int s = 0; s < 2; s++) {
        uint32_t b = sb + s * KD_STAGE;
        cpa16(b + sA0, gA0 + s * 32);
        cpa16(b + sA1, gA1 + s * 32);
        cpa16(b + 8192 + sA0, gB0 + s * 32);
        cpa16(b + 8192 + sA1, gB1 + s * 32);
        asm volatile("cp.async.commit_group;" ::: "memory");
    }

    for (int k = 0; k < KD_ITERS; k++) {
        asm volatile("cp.async.wait_group 1;" ::: "memory");
        __syncthreads();
        const int s = k % 3;
        if (k + 2 < KD_ITERS) {
            const int sn = (k + 2) % 3;
            uint32_t b = sb + sn * KD_STAGE;
            cpa16(b + sA0, gA0 + (k + 2) * 32);
            cpa16(b + sA1, gA1 + (k + 2) * 32);
            cpa16(b + 8192 + sA0, gB0 + (k + 2) * 32);
            cpa16(b + 8192 + sA1, gB1 + (k + 2) * 32);
        }
        asm volatile("cp.async.commit_group;" ::: "memory");

        const uint32_t base = sb + s * KD_STAGE;
#pragma unroll
        for (int ks = 0; ks < 2; ks++) {
            uint32_t af[4][4], bf[4][2];
#pragma unroll
            for (int mi = 0; mi < 4; mi++)
                asm volatile(
                    "ldmatrix.sync.aligned.m8n8.x4.shared.b16 {%0,%1,%2,%3}, [%4];"
                    : "=r"(af[mi][0]), "=r"(af[mi][1]), "=r"(af[mi][2]), "=r"(af[mi][3])
                    : "r"(base + adA[mi][ks]));
#pragma unroll
            for (int p = 0; p < 2; p++)
                asm volatile(
                    "ldmatrix.sync.aligned.m8n8.x4.shared.b16 {%0,%1,%2,%3}, [%4];"
                    : "=r"(bf[2 * p][0]), "=r"(bf[2 * p][1]),
                      "=r"(bf[2 * p + 1][0]), "=r"(bf[2 * p + 1][1])
                    : "r"(base + adB[p][ks]));
#pragma unroll
            for (int mi = 0; mi < 4; mi++)
#pragma unroll
                for (int ni = 0; ni < 4; ni++)
                    asm volatile(
                        "mma.sync.aligned.m16n8k16.row.col.f32.f16.f16.f32 "
                        "{%0,%1,%2,%3}, {%4,%5,%6,%7}, {%8,%9}, {%0,%1,%2,%3};"
                        : "+f"(acc[mi][ni][0]), "+f"(acc[mi][ni][1]),
                          "+f"(acc[mi][ni][2]), "+f"(acc[mi][ni][3])
                        : "r"(af[mi][0]), "r"(af[mi][1]), "r"(af[mi][2]), "r"(af[mi][3]),
                          "r"(bf[ni][0]), "r"(bf[ni][1]));
        }
    }

    // epilogue: bias + float2 stores
    const int gm0 = bm * 128 + warp_m * 64 + (lane >> 2);
#pragma unroll
    for (int mi = 0; mi < 4; mi++) {
#pragma unroll
        for (int ni = 0; ni < 4; ni++) {
            int col = bn * 128 + warp_n * 32 + ni * 8 + (lane & 3) * 2;
            float b0 = __ldg(bias + col), b1 = __ldg(bias + col + 1);
            int r = gm0 + mi * 16;
            float2 v0 = make_float2(acc[mi][ni][0] + b0, acc[mi][ni][1] + b1);
            float2 v1 = make_float2(acc[mi][ni][2] + b0, acc[mi][ni][3] + b1);
            *(float2*)(C + (size_t)r * NDIM + col) = v0;
            *(float2*)(C + (size_t)(r + 8) * NDIM + col) = v1;
        }
    }
}

// ---------------------------------------------------------------------------
// launch
// inputs: 0 hidden, 1 slot_w, 2 slot_b, 3 leaf_logits, 4 node_params,
//         5 out_w, 6 out_b ; output float32 [4096,1024]
// ---------------------------------------------------------------------------
extern "C" void kernel_launch(void* const* d_in, const int* in_sizes, int n_in,
                              void* d_out, int out_size) {
    const float* hidden      = (const float*)d_in[0];
    const float* slot_w      = (const float*)d_in[1];
    const float* slot_b      = (const float*)d_in[2];
    const float* leaf_logits = (const float*)d_in[3];
    const float* node_params = (const float*)d_in[4];
    const float* out_w       = (const float*)d_in[5];
    const float* out_b       = (const float*)d_in[6];
    float* out = (float*)d_out;

    float*  basisT; cudaGetSymbolAddress((void**)&basisT, g_basisT);
    float*  sel;    cudaGetSymbolAddress((void**)&sel,    g_sel);
    __half* roots;  cudaGetSymbolAddress((void**)&roots,  g_roots);
    __half* outwT;  cudaGetSymbolAddress((void**)&outwT,  g_outwT);

    kA<<<NTOK / 8, 256>>>(hidden, slot_w, slot_b, basisT);
    kB<<<(NW * 8) / 256, 256>>>(leaf_logits, sel);
    dim3 gt(NDIM / 32, NW / 32);
    kT<<<gt, dim3(32, 8)>>>(out_w, outwT);
    dim3 gc(NW / 128, NTOK / 128);
    kC<<<gc, 256>>>(node_params, sel, basisT, roots);
    dim3 gd(NDIM / 128, NTOK / 128);
    kD<<<gd, 256>>>(roots, outwT, out_b, out);
}